// round 4
// baseline (speedup 1.0000x reference)
#include <cuda_runtime.h>
#include <cstdint>

#define N_USERS 50000
#define N_ITEMS 100000
#define N_NODES (N_USERS + N_ITEMS)
#define D 64
#define EPS 1e-6f
#define E_MAX 2400000
#define SCAN_BLOCK 1024
#define MAX_SCAN_BLOCKS ((N_NODES + SCAN_BLOCK - 1) / SCAN_BLOCK)   // 147

// ---------------------------------------------------------------------------
// Static scratch (allocation-free). Device symbols are ONLY referenced from
// device code (host-side use passes the host shadow address via ATS — R2 bug).
// ---------------------------------------------------------------------------
__device__ float g_embs[4][N_NODES * D];       // layer 0..3 embeddings
__device__ int   g_cnt[N_NODES];               // per-row edge counts
__device__ int   g_incl[N_NODES];              // per-block inclusive scan
__device__ int   g_blk[MAX_SCAN_BLOCKS];       // block sums -> block offsets
__device__ int   g_row_ptr[N_NODES + 1];       // CSR row pointers
__device__ int   g_row_fill[N_NODES];          // atomic cursors for scatter
__device__ int2  g_csr_edge[E_MAX];            // packed {col, val-bits}
__device__ int   g_is64;                       // index dtype flag

// ---------------------------------------------------------------------------
// Index dtype detection (int64 vs int32)
// ---------------------------------------------------------------------------
__global__ void detect_kernel(const void* rows, int n) {
    if (blockIdx.x == 0 && threadIdx.x == 0) {
        const long long* p = (const long long*)rows;
        int ok = 1;
        int lim = (n < 64) ? n : 64;
        for (int i = 0; i < lim; i++) {
            long long v = p[i];
            if (v < 0 || v >= (long long)N_NODES) { ok = 0; break; }
        }
        g_is64 = ok;
    }
}

__device__ __forceinline__ int load_idx(const void* p, int e) {
    if (g_is64) return (int)((const long long*)p)[e];
    return ((const int*)p)[e];
}

// ---------------------------------------------------------------------------
// CSR build
// ---------------------------------------------------------------------------
__global__ void zero_cnt_kernel() {
    int i = blockIdx.x * blockDim.x + threadIdx.x;
    if (i < N_NODES) g_cnt[i] = 0;
}

__global__ void hist_kernel(const void* __restrict__ rows, int n_edges) {
    int e = blockIdx.x * blockDim.x + threadIdx.x;
    if (e >= n_edges) return;
    atomicAdd(&g_cnt[load_idx(rows, e)], 1);
}

// Inclusive scan within blocks of SCAN_BLOCK, Hillis-Steele.
__global__ void scan1_kernel() {
    __shared__ int sh[SCAN_BLOCK];
    int i = blockIdx.x * SCAN_BLOCK + threadIdx.x;
    int v = (i < N_NODES) ? g_cnt[i] : 0;
    sh[threadIdx.x] = v;
    __syncthreads();
    #pragma unroll
    for (int off = 1; off < SCAN_BLOCK; off <<= 1) {
        int t = (threadIdx.x >= off) ? sh[threadIdx.x - off] : 0;
        __syncthreads();
        sh[threadIdx.x] += t;
        __syncthreads();
    }
    if (i < N_NODES) g_incl[i] = sh[threadIdx.x];
    if (threadIdx.x == SCAN_BLOCK - 1) g_blk[blockIdx.x] = sh[threadIdx.x];
}

// Parallel exclusive scan over the ~147 block sums: one 256-thread block,
// Hillis-Steele in smem. Replaces the R3 single-thread serial loop
// (~147 dependent global round-trips ~= 45-50us of pure latency).
__global__ void scan2_kernel(int nb) {
    __shared__ int sh[256];
    int t = threadIdx.x;
    int v = (t < nb) ? g_blk[t] : 0;
    sh[t] = v;
    __syncthreads();
    #pragma unroll
    for (int off = 1; off < 256; off <<= 1) {
        int u = (t >= off) ? sh[t - off] : 0;
        __syncthreads();
        sh[t] += u;
        __syncthreads();
    }
    if (t < nb) g_blk[t] = sh[t] - v;   // exclusive
}

// row_ptr[i] = exclusive prefix; row_ptr[N] = total; init cursors.
__global__ void scan3_kernel() {
    int i = blockIdx.x * blockDim.x + threadIdx.x;
    if (i >= N_NODES) return;
    int inc = g_incl[i] + g_blk[i / SCAN_BLOCK];
    int exc = inc - g_cnt[i];
    g_row_ptr[i] = exc;
    g_row_fill[i] = exc;
    if (i == N_NODES - 1) g_row_ptr[N_NODES] = inc;
}

__global__ void scatter_kernel(const void* __restrict__ rows,
                               const void* __restrict__ cols,
                               const float* __restrict__ vals,
                               int n_edges) {
    int e = blockIdx.x * blockDim.x + threadIdx.x;
    if (e >= n_edges) return;
    int r = load_idx(rows, e);
    int c = load_idx(cols, e);
    float v = vals[e];
    int pos = atomicAdd(&g_row_fill[r], 1);
    g_csr_edge[pos] = make_int2(c, __float_as_int(v));
}

// ---------------------------------------------------------------------------
// Init: g_embs[0] = concat(user_emb, item_emb)
// ---------------------------------------------------------------------------
__global__ void init_kernel(const float* __restrict__ user_emb,
                            const float* __restrict__ item_emb) {
    int i = blockIdx.x * blockDim.x + threadIdx.x;   // float4 index
    const int total4 = N_NODES * D / 4;
    if (i >= total4) return;
    const int usplit = N_USERS * D / 4;
    float4 v = (i < usplit) ? ((const float4*)user_emb)[i]
                            : ((const float4*)item_emb)[i - usplit];
    ((float4*)g_embs[0])[i] = v;
}

// ---------------------------------------------------------------------------
// Fused layer: per-node CSR gather-sum + growth gating + write next layer.
// One warp per node; lane owns a float2 slice. 4-way unroll for MLP; packed
// 8B edge loads. Layer index passed as int (device-symbol addressing stays
// in device code).
// ---------------------------------------------------------------------------
__global__ void layer_kernel(int l) {
    int node = blockIdx.x * (blockDim.x >> 5) + (threadIdx.x >> 5);
    int lane = threadIdx.x & 31;
    if (node >= N_NODES) return;

    const float2* base = (const float2*)g_embs[l];
    float2*       outp = (float2*)g_embs[l + 1];

    int beg = __ldg(&g_row_ptr[node]);
    int end = __ldg(&g_row_ptr[node + 1]);

    float2 acc = make_float2(0.f, 0.f);

    int i = beg;
    for (; i + 3 < end; i += 4) {
        int2 e0 = __ldg(&g_csr_edge[i]);
        int2 e1 = __ldg(&g_csr_edge[i + 1]);
        int2 e2 = __ldg(&g_csr_edge[i + 2]);
        int2 e3 = __ldg(&g_csr_edge[i + 3]);
        float2 x0 = __ldg(&base[e0.x * 32 + lane]);
        float2 x1 = __ldg(&base[e1.x * 32 + lane]);
        float2 x2 = __ldg(&base[e2.x * 32 + lane]);
        float2 x3 = __ldg(&base[e3.x * 32 + lane]);
        float v0 = __int_as_float(e0.y), v1 = __int_as_float(e1.y);
        float v2 = __int_as_float(e2.y), v3 = __int_as_float(e3.y);
        acc.x += v0 * x0.x; acc.y += v0 * x0.y;
        acc.x += v1 * x1.x; acc.y += v1 * x1.y;
        acc.x += v2 * x2.x; acc.y += v2 * x2.y;
        acc.x += v3 * x3.x; acc.y += v3 * x3.y;
    }
    for (; i < end; i++) {
        int2 e = __ldg(&g_csr_edge[i]);
        float2 x = __ldg(&base[e.x * 32 + lane]);
        float v = __int_as_float(e.y);
        acc.x += v * x.x;
        acc.y += v * x.y;
    }

    float2 o = base[node * 32 + lane];

    float dx = o.x - acc.x + EPS;
    float dy = o.y - acc.y + EPS;
    float s = dx * dx + dy * dy;
    #pragma unroll
    for (int off = 16; off; off >>= 1)
        s += __shfl_xor_sync(0xFFFFFFFFu, s, off);

    float osn   = sqrtf(s);
    float dnew  = log1pf(osn);
    float inv   = 1.0f / (1.0f + dnew);
    float w_old = inv;
    float w_new = dnew * inv;

    float2 r;
    r.x = w_old * o.x + w_new * acc.x;
    r.y = w_old * o.y + w_new * acc.y;
    outp[node * 32 + lane] = r;
}

// ---------------------------------------------------------------------------
// Gather: out row = mean over the 4 layer embeddings of the selected node.
// ---------------------------------------------------------------------------
__global__ void gather_kernel(const void* __restrict__ user_id,
                              const void* __restrict__ item_id,
                              float* __restrict__ out,
                              int n_ids) {
    int i = blockIdx.x * (blockDim.x >> 5) + (threadIdx.x >> 5);
    int lane = threadIdx.x & 31;
    if (i >= 2 * n_ids) return;

    int node;
    if (i < n_ids) node = load_idx(user_id, i);
    else           node = N_USERS + load_idx(item_id, i - n_ids);

    int off = node * 32 + lane;
    float2 a0 = ((const float2*)g_embs[0])[off];
    float2 a1 = ((const float2*)g_embs[1])[off];
    float2 a2 = ((const float2*)g_embs[2])[off];
    float2 a3 = ((const float2*)g_embs[3])[off];
    float2 r;
    r.x = (a0.x + a1.x + a2.x + a3.x) * 0.25f;
    r.y = (a0.y + a1.y + a2.y + a3.y) * 0.25f;
    ((float2*)(out + (long long)i * D))[lane] = r;
}

// ---------------------------------------------------------------------------
// kernel_launch
// ---------------------------------------------------------------------------
extern "C" void kernel_launch(void* const* d_in, const int* in_sizes, int n_in,
                              void* d_out, int out_size) {
    const float* user_emb = (const float*)d_in[0];
    const float* item_emb = (const float*)d_in[1];
    const float* adj_vals = (const float*)d_in[2];
    const void*  adj_rows = d_in[3];
    const void*  adj_cols = d_in[4];
    const void*  user_id  = d_in[5];
    const void*  item_id  = d_in[6];
    float* out = (float*)d_out;

    int n_edges = in_sizes[3];
    if (n_edges > E_MAX) n_edges = E_MAX;
    int n_ids = in_sizes[5];

    detect_kernel<<<1, 32>>>(adj_rows, n_edges);

    // CSR build
    zero_cnt_kernel<<<(N_NODES + 255) / 256, 256>>>();
    hist_kernel<<<(n_edges + 255) / 256, 256>>>(adj_rows, n_edges);
    int nb = (N_NODES + SCAN_BLOCK - 1) / SCAN_BLOCK;
    scan1_kernel<<<nb, SCAN_BLOCK>>>();
    scan2_kernel<<<1, 256>>>(nb);
    scan3_kernel<<<(N_NODES + 255) / 256, 256>>>();
    scatter_kernel<<<(n_edges + 255) / 256, 256>>>(adj_rows, adj_cols, adj_vals, n_edges);

    // emb0
    {
        int total4 = N_NODES * D / 4;
        init_kernel<<<(total4 + 255) / 256, 256>>>(user_emb, item_emb);
    }

    // 3 fused layers: warp per node, 8 nodes per 256-thread block
    int layer_blocks = (N_NODES + 7) / 8;
    layer_kernel<<<layer_blocks, 256>>>(0);
    layer_kernel<<<layer_blocks, 256>>>(1);
    layer_kernel<<<layer_blocks, 256>>>(2);

    // final gather + mean
    int gather_rows = 2 * n_ids;
    gather_kernel<<<(gather_rows + 7) / 8, 256>>>(user_id, item_id, out, n_ids);
}

// round 5
// speedup vs baseline: 1.1529x; 1.1529x over previous
#include <cuda_runtime.h>
#include <cstdint>

#define N_USERS 50000
#define N_ITEMS 100000
#define N_NODES (N_USERS + N_ITEMS)
#define D 64
#define EPS 1e-6f
#define E_MAX 2400000
#define SCAN_BLOCK 1024
#define MAX_SCAN_BLOCKS ((N_NODES + SCAN_BLOCK - 1) / SCAN_BLOCK)   // 147

// ---------------------------------------------------------------------------
// Static scratch (allocation-free). Device symbols are ONLY referenced from
// device code (host-side use passes the host shadow address via ATS — R2 bug).
// ---------------------------------------------------------------------------
__device__ float g_embs[4][N_NODES * D];       // layer 0..3 embeddings
__device__ int   g_cnt[N_NODES];               // per-row edge counts
__device__ int   g_incl[N_NODES];              // per-block inclusive scan
__device__ int   g_blk[MAX_SCAN_BLOCKS];       // block sums -> block offsets
__device__ int   g_row_ptr[N_NODES + 1];       // CSR row pointers
__device__ int   g_row_fill[N_NODES];          // atomic cursors for scatter
__device__ int   g_csr_col[E_MAX];             // CSR column indices
__device__ float g_csr_val[E_MAX];             // CSR values
__device__ int   g_is64;                       // index dtype flag

// ---------------------------------------------------------------------------
// Index dtype detection (int64 vs int32)
// ---------------------------------------------------------------------------
__global__ void detect_kernel(const void* rows, int n) {
    if (blockIdx.x == 0 && threadIdx.x == 0) {
        const long long* p = (const long long*)rows;
        int ok = 1;
        int lim = (n < 64) ? n : 64;
        for (int i = 0; i < lim; i++) {
            long long v = p[i];
            if (v < 0 || v >= (long long)N_NODES) { ok = 0; break; }
        }
        g_is64 = ok;
    }
}

__device__ __forceinline__ int load_idx(const void* p, int e) {
    if (g_is64) return (int)((const long long*)p)[e];
    return ((const int*)p)[e];
}

// ---------------------------------------------------------------------------
// CSR build
// ---------------------------------------------------------------------------
__global__ void zero_cnt_kernel() {
    int i = blockIdx.x * blockDim.x + threadIdx.x;
    if (i < N_NODES) g_cnt[i] = 0;
}

__global__ void hist_kernel(const void* __restrict__ rows, int n_edges) {
    int e = blockIdx.x * blockDim.x + threadIdx.x;
    if (e >= n_edges) return;
    atomicAdd(&g_cnt[load_idx(rows, e)], 1);
}

// Inclusive scan within blocks of SCAN_BLOCK, Hillis-Steele.
__global__ void scan1_kernel() {
    __shared__ int sh[SCAN_BLOCK];
    int i = blockIdx.x * SCAN_BLOCK + threadIdx.x;
    int v = (i < N_NODES) ? g_cnt[i] : 0;
    sh[threadIdx.x] = v;
    __syncthreads();
    #pragma unroll
    for (int off = 1; off < SCAN_BLOCK; off <<= 1) {
        int t = (threadIdx.x >= off) ? sh[threadIdx.x - off] : 0;
        __syncthreads();
        sh[threadIdx.x] += t;
        __syncthreads();
    }
    if (i < N_NODES) g_incl[i] = sh[threadIdx.x];
    if (threadIdx.x == SCAN_BLOCK - 1) g_blk[blockIdx.x] = sh[threadIdx.x];
}

// Parallel exclusive scan over the ~147 block sums: one 256-thread block,
// Hillis-Steele in smem (replaces the single-thread serial loop of R3).
__global__ void scan2_kernel(int nb) {
    __shared__ int sh[256];
    int t = threadIdx.x;
    int v = (t < nb) ? g_blk[t] : 0;
    sh[t] = v;
    __syncthreads();
    #pragma unroll
    for (int off = 1; off < 256; off <<= 1) {
        int u = (t >= off) ? sh[t - off] : 0;
        __syncthreads();
        sh[t] += u;
        __syncthreads();
    }
    if (t < nb) g_blk[t] = sh[t] - v;   // exclusive
}

// row_ptr[i] = exclusive prefix; row_ptr[N] = total; init cursors.
__global__ void scan3_kernel() {
    int i = blockIdx.x * blockDim.x + threadIdx.x;
    if (i >= N_NODES) return;
    int inc = g_incl[i] + g_blk[i / SCAN_BLOCK];
    int exc = inc - g_cnt[i];
    g_row_ptr[i] = exc;
    g_row_fill[i] = exc;
    if (i == N_NODES - 1) g_row_ptr[N_NODES] = inc;
}

__global__ void scatter_kernel(const void* __restrict__ rows,
                               const void* __restrict__ cols,
                               const float* __restrict__ vals,
                               int n_edges) {
    int e = blockIdx.x * blockDim.x + threadIdx.x;
    if (e >= n_edges) return;
    int r = load_idx(rows, e);
    int c = load_idx(cols, e);
    float v = vals[e];
    int pos = atomicAdd(&g_row_fill[r], 1);
    g_csr_col[pos] = c;
    g_csr_val[pos] = v;
}

// ---------------------------------------------------------------------------
// Init: g_embs[0] = concat(user_emb, item_emb)
// ---------------------------------------------------------------------------
__global__ void init_kernel(const float* __restrict__ user_emb,
                            const float* __restrict__ item_emb) {
    int i = blockIdx.x * blockDim.x + threadIdx.x;   // float4 index
    const int total4 = N_NODES * D / 4;
    if (i >= total4) return;
    const int usplit = N_USERS * D / 4;
    float4 v = (i < usplit) ? ((const float4*)user_emb)[i]
                            : ((const float4*)item_emb)[i - usplit];
    ((float4*)g_embs[0])[i] = v;
}

// ---------------------------------------------------------------------------
// Fused layer (R3-proven form): per-node CSR gather-sum + growth gating.
// One warp per node; lane owns a float2 slice; 2-way unroll.
// ---------------------------------------------------------------------------
__global__ void layer_kernel(int l) {
    int node = blockIdx.x * (blockDim.x >> 5) + (threadIdx.x >> 5);
    int lane = threadIdx.x & 31;
    if (node >= N_NODES) return;

    const float2* base = (const float2*)g_embs[l];
    float2*       outp = (float2*)g_embs[l + 1];

    int beg = __ldg(&g_row_ptr[node]);
    int end = __ldg(&g_row_ptr[node + 1]);

    float2 acc = make_float2(0.f, 0.f);

    int i = beg;
    for (; i + 1 < end; i += 2) {
        int   c0 = __ldg(&g_csr_col[i]);
        int   c1 = __ldg(&g_csr_col[i + 1]);
        float v0 = __ldg(&g_csr_val[i]);
        float v1 = __ldg(&g_csr_val[i + 1]);
        float2 x0 = base[c0 * 32 + lane];
        float2 x1 = base[c1 * 32 + lane];
        acc.x += v0 * x0.x + v1 * x1.x;
        acc.y += v0 * x0.y + v1 * x1.y;
    }
    if (i < end) {
        int   c = __ldg(&g_csr_col[i]);
        float v = __ldg(&g_csr_val[i]);
        float2 x = base[c * 32 + lane];
        acc.x += v * x.x;
        acc.y += v * x.y;
    }

    float2 o = base[node * 32 + lane];

    float dx = o.x - acc.x + EPS;
    float dy = o.y - acc.y + EPS;
    float s = dx * dx + dy * dy;
    #pragma unroll
    for (int off = 16; off; off >>= 1)
        s += __shfl_xor_sync(0xFFFFFFFFu, s, off);

    float osn   = sqrtf(s);
    float dnew  = log1pf(osn);
    float inv   = 1.0f / (1.0f + dnew);
    float w_old = inv;
    float w_new = dnew * inv;

    float2 r;
    r.x = w_old * o.x + w_new * acc.x;
    r.y = w_old * o.y + w_new * acc.y;
    outp[node * 32 + lane] = r;
}

// ---------------------------------------------------------------------------
// Gather: out row = mean over the 4 layer embeddings of the selected node.
// ---------------------------------------------------------------------------
__global__ void gather_kernel(const void* __restrict__ user_id,
                              const void* __restrict__ item_id,
                              float* __restrict__ out,
                              int n_ids) {
    int i = blockIdx.x * (blockDim.x >> 5) + (threadIdx.x >> 5);
    int lane = threadIdx.x & 31;
    if (i >= 2 * n_ids) return;

    int node;
    if (i < n_ids) node = load_idx(user_id, i);
    else           node = N_USERS + load_idx(item_id, i - n_ids);

    int off = node * 32 + lane;
    float2 a0 = ((const float2*)g_embs[0])[off];
    float2 a1 = ((const float2*)g_embs[1])[off];
    float2 a2 = ((const float2*)g_embs[2])[off];
    float2 a3 = ((const float2*)g_embs[3])[off];
    float2 r;
    r.x = (a0.x + a1.x + a2.x + a3.x) * 0.25f;
    r.y = (a0.y + a1.y + a2.y + a3.y) * 0.25f;
    ((float2*)(out + (long long)i * D))[lane] = r;
}

// ---------------------------------------------------------------------------
// kernel_launch
// ---------------------------------------------------------------------------
extern "C" void kernel_launch(void* const* d_in, const int* in_sizes, int n_in,
                              void* d_out, int out_size) {
    const float* user_emb = (const float*)d_in[0];
    const float* item_emb = (const float*)d_in[1];
    const float* adj_vals = (const float*)d_in[2];
    const void*  adj_rows = d_in[3];
    const void*  adj_cols = d_in[4];
    const void*  user_id  = d_in[5];
    const void*  item_id  = d_in[6];
    float* out = (float*)d_out;

    int n_edges = in_sizes[3];
    if (n_edges > E_MAX) n_edges = E_MAX;
    int n_ids = in_sizes[5];

    detect_kernel<<<1, 32>>>(adj_rows, n_edges);

    // CSR build
    zero_cnt_kernel<<<(N_NODES + 255) / 256, 256>>>();
    hist_kernel<<<(n_edges + 255) / 256, 256>>>(adj_rows, n_edges);
    int nb = (N_NODES + SCAN_BLOCK - 1) / SCAN_BLOCK;
    scan1_kernel<<<nb, SCAN_BLOCK>>>();
    scan2_kernel<<<1, 256>>>(nb);
    scan3_kernel<<<(N_NODES + 255) / 256, 256>>>();
    scatter_kernel<<<(n_edges + 255) / 256, 256>>>(adj_rows, adj_cols, adj_vals, n_edges);

    // emb0
    {
        int total4 = N_NODES * D / 4;
        init_kernel<<<(total4 + 255) / 256, 256>>>(user_emb, item_emb);
    }

    // 3 fused layers: warp per node, 8 nodes per 256-thread block
    int layer_blocks = (N_NODES + 7) / 8;
    layer_kernel<<<layer_blocks, 256>>>(0);
    layer_kernel<<<layer_blocks, 256>>>(1);
    layer_kernel<<<layer_blocks, 256>>>(2);

    // final gather + mean
    int gather_rows = 2 * n_ids;
    gather_kernel<<<(gather_rows + 7) / 8, 256>>>(user_id, item_id, out, n_ids);
}